// round 9
// baseline (speedup 1.0000x reference)
#include <cuda_runtime.h>

#define SEQL 20
#define EMB  20
#define NMAX 671744
#define EMAX 4000000
#define NBATCH 8192
#define HID  300
#define NC   22
#define LAT  1640   // 82*20

// ---------------- scratch (static device globals; no runtime alloc) -------
__device__ int   g_deg[NMAX];
__device__ float g_dinv[NMAX];
__device__ float g_hs[(size_t)NMAX * EMB];    // scaled features / latent
__device__ float g_agg[(size_t)NMAX * EMB];   // aggregation buffer
__device__ int   g_src[EMAX];
__device__ int   g_dst[EMAX];
__device__ float g_fc1[(size_t)NBATCH * HID];
__device__ int   g_is64;

// ---------------- helpers -------------------------------------------------
__device__ __forceinline__ unsigned long long pack2(float a, float b) {
    unsigned long long r;
    asm("mov.b64 %0, {%1, %2};" : "=l"(r)
        : "r"(__float_as_uint(a)), "r"(__float_as_uint(b)));
    return r;
}
__device__ __forceinline__ unsigned long long fma2(unsigned long long a,
                                                   unsigned long long b,
                                                   unsigned long long c) {
    unsigned long long d;
    asm("fma.rn.f32x2 %0, %1, %2, %3;" : "=l"(d) : "l"(a), "l"(b), "l"(c));
    return d;
}
__device__ __forceinline__ float2 unpack2(unsigned long long v) {
    float x, y;
    asm("mov.b64 {%0, %1}, %2;" : "=f"(x), "=f"(y) : "l"(v));
    return make_float2(x, y);
}
__device__ __forceinline__ void red_add_v4(float* p, float4 v) {
    asm volatile("red.global.add.v4.f32 [%0], {%1,%2,%3,%4};"
                 :: "l"(p), "f"(v.x), "f"(v.y), "f"(v.z), "f"(v.w) : "memory");
}

// ---- launch 1: dtype detect + deg := 1 (self loop) -----------------------
__global__ void k_init(const int* __restrict__ ei32, int n) {
    int i = blockIdx.x * blockDim.x + threadIdx.x;
    if (i < n) g_deg[i] = 1;           // self loop
    if (blockIdx.x == 0 && threadIdx.x == 0) {
        int all0 = 1;
        for (int q = 1; q < 257; q += 2)
            if (ei32[q] != 0) { all0 = 0; break; }
        g_is64 = all0;   // int64 little-endian: high words of small values are 0
    }
}

// ---- launch 2: stage edges to int32 + degree count -----------------------
__global__ void k_edges_prep(const void* __restrict__ eiv, int E) {
    int e = blockIdx.x * blockDim.x + threadIdx.x;
    if (e >= E) return;
    int s, d;
    if (g_is64) {
        const long long* p = (const long long*)eiv;
        s = (int)p[e];
        d = (int)p[(size_t)E + e];
    } else {
        const int* p = (const int*)eiv;
        s = p[e];
        d = p[E + e];
    }
    g_src[e] = s;
    g_dst[e] = d;
    atomicAdd(&g_deg[d], 1);
}

// ---- launch 3: hs = (x @ W1) * dinv ;  agg = hs (self-loop pre-seed) -----
__global__ __launch_bounds__(256) void k_layer1(const float* __restrict__ x,
                                                const float* __restrict__ W,
                                                int n) {
    __shared__ __align__(16) float sW[SEQL * EMB];
    for (int t = threadIdx.x; t < SEQL * EMB; t += 256) sW[t] = W[t];
    __syncthreads();
    int i = blockIdx.x * 256 + threadIdx.x;
    if (i >= n) return;
    float dinv = rsqrtf((float)g_deg[i]);
    g_dinv[i] = dinv;
    float xi[SEQL];
    const float4* xp = (const float4*)(x + (size_t)i * SEQL);
#pragma unroll
    for (int q = 0; q < SEQL / 4; q++) {
        float4 v = __ldg(xp + q);
        xi[4*q] = v.x; xi[4*q+1] = v.y; xi[4*q+2] = v.z; xi[4*q+3] = v.w;
    }
    float o[EMB];
#pragma unroll
    for (int j = 0; j < EMB; j++) o[j] = 0.f;
#pragma unroll
    for (int k = 0; k < SEQL; k++) {
        float xk = xi[k];
#pragma unroll
        for (int q = 0; q < EMB / 4; q++) {
            float4 w = *(const float4*)&sW[k * EMB + 4 * q];
            o[4*q]   = fmaf(xk, w.x, o[4*q]);
            o[4*q+1] = fmaf(xk, w.y, o[4*q+1]);
            o[4*q+2] = fmaf(xk, w.z, o[4*q+2]);
            o[4*q+3] = fmaf(xk, w.w, o[4*q+3]);
        }
    }
    float4* hp = (float4*)(g_hs  + (size_t)i * EMB);
    float4* ap = (float4*)(g_agg + (size_t)i * EMB);
#pragma unroll
    for (int q = 0; q < EMB / 4; q++) {
        float4 v = make_float4(o[4*q]*dinv, o[4*q+1]*dinv, o[4*q+2]*dinv, o[4*q+3]*dinv);
        hp[q] = v; ap[q] = v;
    }
}

// ---- launch 4 (ncu slot): agg[dst] += hs[src] (staged int32, RED.128 x5) -
__global__ __launch_bounds__(256) void k_scatter(int E) {
    int e = blockIdx.x * blockDim.x + threadIdx.x;
    if (e >= E) return;
    int s = g_src[e], d = g_dst[e];
    const float4* hp = (const float4*)(g_hs + (size_t)s * EMB);
    float* ap = g_agg + (size_t)d * EMB;
#pragma unroll
    for (int q = 0; q < EMB / 4; q++) {
        float4 v = __ldg(hp + q);
        red_add_v4(ap + 4 * q, v);
    }
}

// ---- t = relu(agg*dinv + b1);  o = (t @ W2)*dinv;  hs = o;  agg = o ------
__global__ __launch_bounds__(256) void k_layer2(const float* __restrict__ b1,
                                                const float* __restrict__ W,
                                                int n) {
    __shared__ __align__(16) float sW[EMB * EMB];
    __shared__ float sb[EMB];
    for (int t = threadIdx.x; t < EMB * EMB; t += 256) sW[t] = W[t];
    if (threadIdx.x < EMB) sb[threadIdx.x] = b1[threadIdx.x];
    __syncthreads();
    int i = blockIdx.x * 256 + threadIdx.x;
    if (i >= n) return;
    float dinv = g_dinv[i];
    float ti[EMB];
    const float4* ap_in = (const float4*)(g_agg + (size_t)i * EMB);
#pragma unroll
    for (int q = 0; q < EMB / 4; q++) {
        float4 v = ap_in[q];
        ti[4*q]   = fmaxf(fmaf(v.x, dinv, sb[4*q]),   0.f);
        ti[4*q+1] = fmaxf(fmaf(v.y, dinv, sb[4*q+1]), 0.f);
        ti[4*q+2] = fmaxf(fmaf(v.z, dinv, sb[4*q+2]), 0.f);
        ti[4*q+3] = fmaxf(fmaf(v.w, dinv, sb[4*q+3]), 0.f);
    }
    float o[EMB];
#pragma unroll
    for (int j = 0; j < EMB; j++) o[j] = 0.f;
#pragma unroll
    for (int k = 0; k < EMB; k++) {
        float tk = ti[k];
#pragma unroll
        for (int q = 0; q < EMB / 4; q++) {
            float4 w = *(const float4*)&sW[k * EMB + 4 * q];
            o[4*q]   = fmaf(tk, w.x, o[4*q]);
            o[4*q+1] = fmaf(tk, w.y, o[4*q+1]);
            o[4*q+2] = fmaf(tk, w.z, o[4*q+2]);
            o[4*q+3] = fmaf(tk, w.w, o[4*q+3]);
        }
    }
    float4* hp = (float4*)(g_hs  + (size_t)i * EMB);
    float4* ap = (float4*)(g_agg + (size_t)i * EMB);
#pragma unroll
    for (int q = 0; q < EMB / 4; q++) {
        float4 v = make_float4(o[4*q]*dinv, o[4*q+1]*dinv, o[4*q+2]*dinv, o[4*q+3]*dinv);
        hp[q] = v; ap[q] = v;
    }
}

// ---- latent = relu(agg*dinv + b2)   -> stored into g_hs ------------------
__global__ __launch_bounds__(256) void k_final(const float* __restrict__ b2, int n) {
    __shared__ float sb[EMB];
    if (threadIdx.x < EMB) sb[threadIdx.x] = b2[threadIdx.x];
    __syncthreads();
    int i = blockIdx.x * 256 + threadIdx.x;
    if (i >= n) return;
    float dinv = g_dinv[i];
    const float4* ap = (const float4*)(g_agg + (size_t)i * EMB);
    float4* hp = (float4*)(g_hs + (size_t)i * EMB);
#pragma unroll
    for (int q = 0; q < EMB / 4; q++) {
        float4 v = ap[q];
        v.x = fmaxf(fmaf(v.x, dinv, sb[4*q]),   0.f);
        v.y = fmaxf(fmaf(v.y, dinv, sb[4*q+1]), 0.f);
        v.z = fmaxf(fmaf(v.z, dinv, sb[4*q+2]), 0.f);
        v.w = fmaxf(fmaf(v.w, dinv, sb[4*q+3]), 0.f);
        hp[q] = v;
    }
}

// fc1: C[8192,300] = relu(latent[8192,1640] @ Wf[1640,300] + bf)
// BM=128 BN=64 BK=8, 128 threads, TM=8 TN=8.
// A pairs come directly from 64-bit lanes of LDS.128 (4-distinct-addr
// broadcast = 1 wavefront); only B needs 8 pack movs per 32 fma2.
#define BM 128
#define BN 64
#define BK 8
__global__ __launch_bounds__(128) void k_fc1(const float* __restrict__ Wf,
                                             const float* __restrict__ bf) {
    __shared__ __align__(16) float As[BK][BM + 4];
    __shared__ __align__(16) float Bs[BK][BN + 4];
    const int tid  = threadIdx.x;
    const int row0 = blockIdx.x * BM;
    const int col0 = blockIdx.y * BN;
    const int tm = (tid >> 3) * 8;      // 16 groups of 8 rows
    const int tn = (tid & 7) * 8;       // 8 groups of 8 cols
    const int arow = tid >> 1;          // 0..63 (+64 for second row)
    const int ak   = (tid & 1) * 4;     // 0 or 4
    const int brow = tid >> 4;          // 0..7
    const int bc   = (tid & 15) * 4;    // 0..60

    unsigned long long acc[4][8];       // [m-pair][col]
#pragma unroll
    for (int p = 0; p < 4; p++)
#pragma unroll
        for (int q = 0; q < 8; q++) acc[p][q] = 0ULL;

    for (int k0 = 0; k0 < LAT; k0 += BK) {
        // A: rows arow and arow+64, 4 k's each
        const float* abase = g_hs + (size_t)(row0 + arow) * LAT + (k0 + ak);
        float4 va0 = *(const float4*)abase;
        float4 va1 = *(const float4*)(abase + (size_t)64 * LAT);
        As[ak + 0][arow] = va0.x;
        As[ak + 1][arow] = va0.y;
        As[ak + 2][arow] = va0.z;
        As[ak + 3][arow] = va0.w;
        As[ak + 0][arow + 64] = va1.x;
        As[ak + 1][arow + 64] = va1.y;
        As[ak + 2][arow + 64] = va1.z;
        As[ak + 3][arow + 64] = va1.w;
        // B: 8 rows x 64 cols, 1 float4 per thread
        {
            int gc = col0 + bc;
            float4 vb = make_float4(0.f, 0.f, 0.f, 0.f);
            if (gc < HID)
                vb = *(const float4*)(Wf + (size_t)(k0 + brow) * HID + gc);
            *(float4*)&Bs[brow][bc] = vb;
        }
        __syncthreads();
#pragma unroll
        for (int k = 0; k < BK; k++) {
            ulonglong2 a01 = *(const ulonglong2*)&As[k][tm];      // pairs (m,m+1)(m+2,m+3)
            ulonglong2 a23 = *(const ulonglong2*)&As[k][tm + 4];  // pairs (m+4..m+7)
            float4 b0 = *(const float4*)&Bs[k][tn];
            float4 b1 = *(const float4*)&Bs[k][tn + 4];
            unsigned long long bb0 = pack2(b0.x, b0.x);
            unsigned long long bb1 = pack2(b0.y, b0.y);
            unsigned long long bb2 = pack2(b0.z, b0.z);
            unsigned long long bb3 = pack2(b0.w, b0.w);
            unsigned long long bb4 = pack2(b1.x, b1.x);
            unsigned long long bb5 = pack2(b1.y, b1.y);
            unsigned long long bb6 = pack2(b1.z, b1.z);
            unsigned long long bb7 = pack2(b1.w, b1.w);
            acc[0][0] = fma2(a01.x, bb0, acc[0][0]);
            acc[0][1] = fma2(a01.x, bb1, acc[0][1]);
            acc[0][2] = fma2(a01.x, bb2, acc[0][2]);
            acc[0][3] = fma2(a01.x, bb3, acc[0][3]);
            acc[0][4] = fma2(a01.x, bb4, acc[0][4]);
            acc[0][5] = fma2(a01.x, bb5, acc[0][5]);
            acc[0][6] = fma2(a01.x, bb6, acc[0][6]);
            acc[0][7] = fma2(a01.x, bb7, acc[0][7]);
            acc[1][0] = fma2(a01.y, bb0, acc[1][0]);
            acc[1][1] = fma2(a01.y, bb1, acc[1][1]);
            acc[1][2] = fma2(a01.y, bb2, acc[1][2]);
            acc[1][3] = fma2(a01.y, bb3, acc[1][3]);
            acc[1][4] = fma2(a01.y, bb4, acc[1][4]);
            acc[1][5] = fma2(a01.y, bb5, acc[1][5]);
            acc[1][6] = fma2(a01.y, bb6, acc[1][6]);
            acc[1][7] = fma2(a01.y, bb7, acc[1][7]);
            acc[2][0] = fma2(a23.x, bb0, acc[2][0]);
            acc[2][1] = fma2(a23.x, bb1, acc[2][1]);
            acc[2][2] = fma2(a23.x, bb2, acc[2][2]);
            acc[2][3] = fma2(a23.x, bb3, acc[2][3]);
            acc[2][4] = fma2(a23.x, bb4, acc[2][4]);
            acc[2][5] = fma2(a23.x, bb5, acc[2][5]);
            acc[2][6] = fma2(a23.x, bb6, acc[2][6]);
            acc[2][7] = fma2(a23.x, bb7, acc[2][7]);
            acc[3][0] = fma2(a23.y, bb0, acc[3][0]);
            acc[3][1] = fma2(a23.y, bb1, acc[3][1]);
            acc[3][2] = fma2(a23.y, bb2, acc[3][2]);
            acc[3][3] = fma2(a23.y, bb3, acc[3][3]);
            acc[3][4] = fma2(a23.y, bb4, acc[3][4]);
            acc[3][5] = fma2(a23.y, bb5, acc[3][5]);
            acc[3][6] = fma2(a23.y, bb6, acc[3][6]);
            acc[3][7] = fma2(a23.y, bb7, acc[3][7]);
        }
        __syncthreads();
    }

    // epilogue: bias + relu, stores in float4 granularity (HID % 4 == 0)
    float bb[8];
#pragma unroll
    for (int q = 0; q < 8; q++) {
        int gc = col0 + tn + q;
        bb[q] = (gc < HID) ? bf[gc] : 0.f;
    }
#pragma unroll
    for (int p = 0; p < 4; p++) {
        float2 u[8];
#pragma unroll
        for (int q = 0; q < 8; q++) u[q] = unpack2(acc[p][q]);
        int r = row0 + tm + 2 * p;
#pragma unroll
        for (int half = 0; half < 2; half++) {
            int gc = col0 + tn + 4 * half;
            if (gc < HID) {
                float4 vlo = make_float4(fmaxf(u[4*half+0].x + bb[4*half+0], 0.f),
                                         fmaxf(u[4*half+1].x + bb[4*half+1], 0.f),
                                         fmaxf(u[4*half+2].x + bb[4*half+2], 0.f),
                                         fmaxf(u[4*half+3].x + bb[4*half+3], 0.f));
                float4 vhi = make_float4(fmaxf(u[4*half+0].y + bb[4*half+0], 0.f),
                                         fmaxf(u[4*half+1].y + bb[4*half+1], 0.f),
                                         fmaxf(u[4*half+2].y + bb[4*half+2], 0.f),
                                         fmaxf(u[4*half+3].y + bb[4*half+3], 0.f));
                *(float4*)(g_fc1 + (size_t)r * HID + gc)       = vlo;
                *(float4*)(g_fc1 + (size_t)(r + 1) * HID + gc) = vhi;
            }
        }
    }
}

// out: [8192,300] @ [300,22] + out_b
__global__ __launch_bounds__(256) void k_out(const float* __restrict__ Wo,
                                             const float* __restrict__ bo,
                                             float* __restrict__ out) {
    __shared__ float sW[HID * NC];
    __shared__ float sb[NC];
    for (int t = threadIdx.x; t < HID * NC; t += 256) sW[t] = Wo[t];
    if (threadIdx.x < NC) sb[threadIdx.x] = bo[threadIdx.x];
    __syncthreads();
    int w = threadIdx.x >> 5, lane = threadIdx.x & 31;
    int rbase = blockIdx.x * 64 + w * 8;
#pragma unroll 1
    for (int r8 = 0; r8 < 8; r8++) {
        int r = rbase + r8;
        const float4* fr4 = (const float4*)(g_fc1 + (size_t)r * HID);
        if (lane < NC) {
            float accv = 0.f;
#pragma unroll 5
            for (int k4 = 0; k4 < HID / 4; k4++) {
                float4 v = fr4[k4];
                int k = 4 * k4;
                accv = fmaf(v.x, sW[(k + 0) * NC + lane], accv);
                accv = fmaf(v.y, sW[(k + 1) * NC + lane], accv);
                accv = fmaf(v.z, sW[(k + 2) * NC + lane], accv);
                accv = fmaf(v.w, sW[(k + 3) * NC + lane], accv);
            }
            out[(size_t)r * NC + lane] = accv + sb[lane];
        }
    }
}

// ---------------- launch --------------------------------------------------
extern "C" void kernel_launch(void* const* d_in, const int* in_sizes, int n_in,
                              void* d_out, int out_size) {
    const float* x    = (const float*)d_in[0];
    const void*  ei   = d_in[1];
    const float* W1   = (const float*)d_in[3];
    const float* b1   = (const float*)d_in[4];
    const float* W2   = (const float*)d_in[5];
    const float* b2   = (const float*)d_in[6];
    const float* fc1W = (const float*)d_in[7];
    const float* fc1b = (const float*)d_in[8];
    const float* outW = (const float*)d_in[9];
    const float* outb = (const float*)d_in[10];
    float* out = (float*)d_out;

    int N = in_sizes[0] / SEQL;
    int E = in_sizes[1] / 2;
    int rows = out_size / NC;                // 8192
    int nb = (N + 255) / 256;
    int eb = (E + 255) / 256;

    k_init<<<nb, 256>>>((const int*)ei, N);     // 1
    k_edges_prep<<<eb, 256>>>(ei, E);           // 2
    k_layer1<<<nb, 256>>>(x, W1, N);            // 3
    k_scatter<<<eb, 256>>>(E);                  // 4  <-- ncu slot (sentinel)
    k_layer2<<<nb, 256>>>(b1, W2, N);           // 5
    k_scatter<<<eb, 256>>>(E);                  // 6
    k_final<<<nb, 256>>>(b2, N);                // 7
    dim3 gfc(rows / BM, (HID + BN - 1) / BN);
    k_fc1<<<gfc, 128>>>(fc1W, fc1b);            // 8
    k_out<<<rows / 64, 256>>>(outW, outb, out); // 9
}

// round 11
// speedup vs baseline: 1.1219x; 1.1219x over previous
#include <cuda_runtime.h>
#include <cuda_fp16.h>

#define SEQL 20
#define EMB  20
#define NMAX 671744
#define EMAX 4000000
#define NBATCH 8192
#define HID  300
#define NC   22
#define LAT  1640   // 82*20

// ---------------- scratch (static device globals; no runtime alloc) -------
__device__ int   g_deg[NMAX];
__device__ float g_dinv[NMAX];
__device__ __align__(16) uint4 g_hsh[(size_t)NMAX * 3];   // fp16 messages, 48B/row (40B valid)
__device__ float g_hs[(size_t)NMAX * EMB];    // fp32 latent (written by k_final)
__device__ float g_agg[(size_t)NMAX * EMB];   // fp32 aggregation buffer
__device__ int   g_src[EMAX];
__device__ int   g_dst[EMAX];
__device__ float g_fc1[(size_t)NBATCH * HID];
__device__ int   g_is64;

// ---------------- helpers -------------------------------------------------
__device__ __forceinline__ unsigned long long pack2(float a, float b) {
    unsigned long long r;
    asm("mov.b64 %0, {%1, %2};" : "=l"(r)
        : "r"(__float_as_uint(a)), "r"(__float_as_uint(b)));
    return r;
}
__device__ __forceinline__ unsigned long long fma2(unsigned long long a,
                                                   unsigned long long b,
                                                   unsigned long long c) {
    unsigned long long d;
    asm("fma.rn.f32x2 %0, %1, %2, %3;" : "=l"(d) : "l"(a), "l"(b), "l"(c));
    return d;
}
__device__ __forceinline__ float2 unpack2(unsigned long long v) {
    float x, y;
    asm("mov.b64 {%0, %1}, %2;" : "=f"(x), "=f"(y) : "l"(v));
    return make_float2(x, y);
}
__device__ __forceinline__ void red_add_v4(float* p, float4 v) {
    asm volatile("red.global.add.v4.f32 [%0], {%1,%2,%3,%4};"
                 :: "l"(p), "f"(v.x), "f"(v.y), "f"(v.z), "f"(v.w) : "memory");
}
// write one node row: o[0..19]*dinv -> fp16x2 packed 48B (+agg fp32 seed)
__device__ __forceinline__ void store_row(int i, const float* o, float dinv) {
    __half2 hh[12];
#pragma unroll
    for (int j = 0; j < 10; j++)
        hh[j] = __floats2half2_rn(o[2*j] * dinv, o[2*j+1] * dinv);
    hh[10] = hh[11] = __float2half2_rn(0.f);
    uint4* hp = &g_hsh[(size_t)i * 3];
    const uint4* src = (const uint4*)hh;
    hp[0] = src[0]; hp[1] = src[1]; hp[2] = src[2];
    float4* ap = (float4*)(g_agg + (size_t)i * EMB);
#pragma unroll
    for (int q = 0; q < EMB / 4; q++)
        ap[q] = make_float4(o[4*q]*dinv, o[4*q+1]*dinv, o[4*q+2]*dinv, o[4*q+3]*dinv);
}

// ---- launch 1: dtype detect + deg := 1 (self loop) -----------------------
__global__ void k_init(const int* __restrict__ ei32, int n) {
    int i = blockIdx.x * blockDim.x + threadIdx.x;
    if (i < n) g_deg[i] = 1;           // self loop
    if (blockIdx.x == 0 && threadIdx.x == 0) {
        int all0 = 1;
        for (int q = 1; q < 257; q += 2)
            if (ei32[q] != 0) { all0 = 0; break; }
        g_is64 = all0;   // int64 little-endian: high words of small values are 0
    }
}

// ---- launch 2: stage edges to int32 + degree count -----------------------
__global__ void k_edges_prep(const void* __restrict__ eiv, int E) {
    int e = blockIdx.x * blockDim.x + threadIdx.x;
    if (e >= E) return;
    int s, d;
    if (g_is64) {
        const long long* p = (const long long*)eiv;
        s = (int)p[e];
        d = (int)p[(size_t)E + e];
    } else {
        const int* p = (const int*)eiv;
        s = p[e];
        d = p[E + e];
    }
    g_src[e] = s;
    g_dst[e] = d;
    atomicAdd(&g_deg[d], 1);
}

// ---- launch 3: msg(fp16) = (x @ W1)*dinv ; agg(fp32) = same (self seed) --
__global__ __launch_bounds__(256) void k_layer1(const float* __restrict__ x,
                                                const float* __restrict__ W,
                                                int n) {
    __shared__ __align__(16) float sW[SEQL * EMB];
    for (int t = threadIdx.x; t < SEQL * EMB; t += 256) sW[t] = W[t];
    __syncthreads();
    int i = blockIdx.x * 256 + threadIdx.x;
    if (i >= n) return;
    float dinv = rsqrtf((float)g_deg[i]);
    g_dinv[i] = dinv;
    float xi[SEQL];
    const float4* xp = (const float4*)(x + (size_t)i * SEQL);
#pragma unroll
    for (int q = 0; q < SEQL / 4; q++) {
        float4 v = __ldg(xp + q);
        xi[4*q] = v.x; xi[4*q+1] = v.y; xi[4*q+2] = v.z; xi[4*q+3] = v.w;
    }
    float o[EMB];
#pragma unroll
    for (int j = 0; j < EMB; j++) o[j] = 0.f;
#pragma unroll
    for (int k = 0; k < SEQL; k++) {
        float xk = xi[k];
#pragma unroll
        for (int q = 0; q < EMB / 4; q++) {
            float4 w = *(const float4*)&sW[k * EMB + 4 * q];
            o[4*q]   = fmaf(xk, w.x, o[4*q]);
            o[4*q+1] = fmaf(xk, w.y, o[4*q+1]);
            o[4*q+2] = fmaf(xk, w.z, o[4*q+2]);
            o[4*q+3] = fmaf(xk, w.w, o[4*q+3]);
        }
    }
    store_row(i, o, dinv);
}

// ---- launch 4 (ncu slot): agg[dst] += msg[src]  (48B fp16 read, fp32 RED)
__global__ __launch_bounds__(256) void k_scatter(int E) {
    int e = blockIdx.x * blockDim.x + threadIdx.x;
    if (e >= E) return;
    int s = g_src[e], d = g_dst[e];
    const uint4* hp = &g_hsh[(size_t)s * 3];
    uint4 u0 = __ldg(hp), u1 = __ldg(hp + 1), u2 = __ldg(hp + 2);
    __half2 hh[12];
    uint4* hv = (uint4*)hh;
    hv[0] = u0; hv[1] = u1; hv[2] = u2;
    float f[EMB];
#pragma unroll
    for (int j = 0; j < 10; j++) {
        float2 t = __half22float2(hh[j]);
        f[2*j] = t.x; f[2*j+1] = t.y;
    }
    float* ap = g_agg + (size_t)d * EMB;
#pragma unroll
    for (int q = 0; q < EMB / 4; q++)
        red_add_v4(ap + 4 * q, make_float4(f[4*q], f[4*q+1], f[4*q+2], f[4*q+3]));
}

// ---- t = relu(agg*dinv + b1);  o = (t @ W2)*dinv -> msg fp16 + agg seed --
__global__ __launch_bounds__(256) void k_layer2(const float* __restrict__ b1,
                                                const float* __restrict__ W,
                                                int n) {
    __shared__ __align__(16) float sW[EMB * EMB];
    __shared__ float sb[EMB];
    for (int t = threadIdx.x; t < EMB * EMB; t += 256) sW[t] = W[t];
    if (threadIdx.x < EMB) sb[threadIdx.x] = b1[threadIdx.x];
    __syncthreads();
    int i = blockIdx.x * 256 + threadIdx.x;
    if (i >= n) return;
    float dinv = g_dinv[i];
    float ti[EMB];
    const float4* ap_in = (const float4*)(g_agg + (size_t)i * EMB);
#pragma unroll
    for (int q = 0; q < EMB / 4; q++) {
        float4 v = ap_in[q];
        ti[4*q]   = fmaxf(fmaf(v.x, dinv, sb[4*q]),   0.f);
        ti[4*q+1] = fmaxf(fmaf(v.y, dinv, sb[4*q+1]), 0.f);
        ti[4*q+2] = fmaxf(fmaf(v.z, dinv, sb[4*q+2]), 0.f);
        ti[4*q+3] = fmaxf(fmaf(v.w, dinv, sb[4*q+3]), 0.f);
    }
    float o[EMB];
#pragma unroll
    for (int j = 0; j < EMB; j++) o[j] = 0.f;
#pragma unroll
    for (int k = 0; k < EMB; k++) {
        float tk = ti[k];
#pragma unroll
        for (int q = 0; q < EMB / 4; q++) {
            float4 w = *(const float4*)&sW[k * EMB + 4 * q];
            o[4*q]   = fmaf(tk, w.x, o[4*q]);
            o[4*q+1] = fmaf(tk, w.y, o[4*q+1]);
            o[4*q+2] = fmaf(tk, w.z, o[4*q+2]);
            o[4*q+3] = fmaf(tk, w.w, o[4*q+3]);
        }
    }
    store_row(i, o, dinv);
}

// ---- latent = relu(agg*dinv + b2)   -> stored fp32 into g_hs -------------
__global__ __launch_bounds__(256) void k_final(const float* __restrict__ b2, int n) {
    __shared__ float sb[EMB];
    if (threadIdx.x < EMB) sb[threadIdx.x] = b2[threadIdx.x];
    __syncthreads();
    int i = blockIdx.x * 256 + threadIdx.x;
    if (i >= n) return;
    float dinv = g_dinv[i];
    const float4* ap = (const float4*)(g_agg + (size_t)i * EMB);
    float4* hp = (float4*)(g_hs + (size_t)i * EMB);
#pragma unroll
    for (int q = 0; q < EMB / 4; q++) {
        float4 v = ap[q];
        v.x = fmaxf(fmaf(v.x, dinv, sb[4*q]),   0.f);
        v.y = fmaxf(fmaf(v.y, dinv, sb[4*q+1]), 0.f);
        v.z = fmaxf(fmaf(v.z, dinv, sb[4*q+2]), 0.f);
        v.w = fmaxf(fmaf(v.w, dinv, sb[4*q+3]), 0.f);
        hp[q] = v;
    }
}

// fc1: C[8192,300] = relu(latent[8192,1640] @ Wf[1640,300] + bf)
// BM=128 BN=64 BK=8, 256 thr, TM=8 TN=4, packed f32x2 FMA (m-pair lanes)
#define BM 128
#define BN 64
#define BK 8
__global__ __launch_bounds__(256) void k_fc1(const float* __restrict__ Wf,
                                             const float* __restrict__ bf) {
    __shared__ __align__(16) float As[BK][BM + 4];
    __shared__ __align__(16) float Bs[BK][BN + 4];
    const int tid  = threadIdx.x;
    const int row0 = blockIdx.x * BM;
    const int col0 = blockIdx.y * BN;
    const int tm = (tid >> 4) * 8;      // 0..120
    const int tn = (tid & 15) * 4;      // 0..60
    const int arow = tid >> 1;          // 0..127
    const int ak   = (tid & 1) * 4;     // 0 or 4
    const int brow = tid >> 4;          // 0..7 (tid<128)
    const int bc   = (tid & 15) * 4;    // 0..60

    unsigned long long acc[4][4];       // [m-pair][col]
#pragma unroll
    for (int p = 0; p < 4; p++)
#pragma unroll
        for (int q = 0; q < 4; q++) acc[p][q] = 0ULL;

    for (int k0 = 0; k0 < LAT; k0 += BK) {
        float4 va = *(const float4*)(g_hs + (size_t)(row0 + arow) * LAT + (k0 + ak));
        As[ak + 0][arow] = va.x;
        As[ak + 1][arow] = va.y;
        As[ak + 2][arow] = va.z;
        As[ak + 3][arow] = va.w;
        if (tid < 128) {
            int gc = col0 + bc;
            float4 vb = make_float4(0.f, 0.f, 0.f, 0.f);
            if (gc < HID)
                vb = *(const float4*)(Wf + (size_t)(k0 + brow) * HID + gc);
            *(float4*)&Bs[brow][bc] = vb;
        }
        __syncthreads();
#pragma unroll
        for (int k = 0; k < BK; k++) {
            float4 a0 = *(const float4*)&As[k][tm];
            float4 a1 = *(const float4*)&As[k][tm + 4];
            float4 bv = *(const float4*)&Bs[k][tn];
            unsigned long long ap0 = pack2(a0.x, a0.y);
            unsigned long long ap1 = pack2(a0.z, a0.w);
            unsigned long long ap2 = pack2(a1.x, a1.y);
            unsigned long long ap3 = pack2(a1.z, a1.w);
            unsigned long long bb0 = pack2(bv.x, bv.x);
            unsigned long long bb1 = pack2(bv.y, bv.y);
            unsigned long long bb2 = pack2(bv.z, bv.z);
            unsigned long long bb3 = pack2(bv.w, bv.w);
            acc[0][0] = fma2(ap0, bb0, acc[0][0]);
            acc[0][1] = fma2(ap0, bb1, acc[0][1]);
            acc[0][2] = fma2(ap0, bb2, acc[0][2]);
            acc[0][3] = fma2(ap0, bb3, acc[0][3]);
            acc[1][0] = fma2(ap1, bb0, acc[1][0]);
            acc[1][1] = fma2(ap1, bb1, acc[1][1]);
            acc[1][2] = fma2(ap1, bb2, acc[1][2]);
            acc[1][3] = fma2(ap1, bb3, acc[1][3]);
            acc[2][0] = fma2(ap2, bb0, acc[2][0]);
            acc[2][1] = fma2(ap2, bb1, acc[2][1]);
            acc[2][2] = fma2(ap2, bb2, acc[2][2]);
            acc[2][3] = fma2(ap2, bb3, acc[2][3]);
            acc[3][0] = fma2(ap3, bb0, acc[3][0]);
            acc[3][1] = fma2(ap3, bb1, acc[3][1]);
            acc[3][2] = fma2(ap3, bb2, acc[3][2]);
            acc[3][3] = fma2(ap3, bb3, acc[3][3]);
        }
        __syncthreads();
    }
    int gc = col0 + tn;
    if (gc < HID) {   // HID%4==0 so the whole float4 is valid
        float bb[4];
#pragma unroll
        for (int q = 0; q < 4; q++) bb[q] = bf[gc + q];
#pragma unroll
        for (int p = 0; p < 4; p++) {
            float2 u0 = unpack2(acc[p][0]);
            float2 u1 = unpack2(acc[p][1]);
            float2 u2 = unpack2(acc[p][2]);
            float2 u3 = unpack2(acc[p][3]);
            int r = row0 + tm + 2 * p;
            float4 vlo = make_float4(fmaxf(u0.x + bb[0], 0.f), fmaxf(u1.x + bb[1], 0.f),
                                     fmaxf(u2.x + bb[2], 0.f), fmaxf(u3.x + bb[3], 0.f));
            float4 vhi = make_float4(fmaxf(u0.y + bb[0], 0.f), fmaxf(u1.y + bb[1], 0.f),
                                     fmaxf(u2.y + bb[2], 0.f), fmaxf(u3.y + bb[3], 0.f));
            *(float4*)(g_fc1 + (size_t)r * HID + gc)       = vlo;
            *(float4*)(g_fc1 + (size_t)(r + 1) * HID + gc) = vhi;
        }
    }
}

// out: [8192,300] @ [300,22] + out_b
__global__ __launch_bounds__(256) void k_out(const float* __restrict__ Wo,
                                             const float* __restrict__ bo,
                                             float* __restrict__ out) {
    __shared__ float sW[HID * NC];
    __shared__ float sb[NC];
    for (int t = threadIdx.x; t < HID * NC; t += 256) sW[t] = Wo[t];
    if (threadIdx.x < NC) sb[threadIdx.x] = bo[threadIdx.x];
    __syncthreads();
    int w = threadIdx.x >> 5, lane = threadIdx.x & 31;
    int rbase = blockIdx.x * 64 + w * 8;
#pragma unroll 1
    for (int r8 = 0; r8 < 8; r8++) {
        int r = rbase + r8;
        const float4* fr4 = (const float4*)(g_fc1 + (size_t)r * HID);
        if (lane < NC) {
            float accv = 0.f;
#pragma unroll 5
            for (int k4 = 0; k4 < HID / 4; k4++) {
                float4 v = fr4[k4];
                int k = 4 * k4;
                accv = fmaf(v.x, sW[(k + 0) * NC + lane], accv);
                accv = fmaf(v.y, sW[(k + 1) * NC + lane], accv);
                accv = fmaf(v.z, sW[(k + 2) * NC + lane], accv);
                accv = fmaf(v.w, sW[(k + 3) * NC + lane], accv);
            }
            out[(size_t)r * NC + lane] = accv + sb[lane];
        }
    }
}

// ---------------- launch --------------------------------------------------
extern "C" void kernel_launch(void* const* d_in, const int* in_sizes, int n_in,
                              void* d_out, int out_size) {
    const float* x    = (const float*)d_in[0];
    const void*  ei   = d_in[1];
    const float* W1   = (const float*)d_in[3];
    const float* b1   = (const float*)d_in[4];
    const float* W2   = (const float*)d_in[5];
    const float* b2   = (const float*)d_in[6];
    const float* fc1W = (const float*)d_in[7];
    const float* fc1b = (const float*)d_in[8];
    const float* outW = (const float*)d_in[9];
    const float* outb = (const float*)d_in[10];
    float* out = (float*)d_out;

    int N = in_sizes[0] / SEQL;
    int E = in_sizes[1] / 2;
    int rows = out_size / NC;                // 8192
    int nb = (N + 255) / 256;
    int eb = (E + 255) / 256;

    k_init<<<nb, 256>>>((const int*)ei, N);     // 1
    k_edges_prep<<<eb, 256>>>(ei, E);           // 2
    k_layer1<<<nb, 256>>>(x, W1, N);            // 3
    k_scatter<<<eb, 256>>>(E);                  // 4  <-- ncu slot
    k_layer2<<<nb, 256>>>(b1, W2, N);           // 5
    k_scatter<<<eb, 256>>>(E);                  // 6
    k_final<<<nb, 256>>>(b2, N);                // 7
    dim3 gfc(rows / BM, (HID + BN - 1) / BN);
    k_fc1<<<gfc, 256>>>(fc1W, fc1b);            // 8
    k_out<<<rows / 64, 256>>>(outW, outb, out); // 9
}

// round 12
// speedup vs baseline: 1.3076x; 1.1655x over previous
#include <cuda_runtime.h>
#include <cuda_fp16.h>

#define SEQL 20
#define EMB  20
#define NMAX 671744
#define EMAX 4000000
#define NBATCH 8192
#define HID  300
#define NC   22
#define LAT  1640   // 82*20

// ---------------- scratch (static device globals; no runtime alloc) -------
__device__ int   g_deg[NMAX];
__device__ float g_dinv[NMAX];
__device__ __align__(16) uint4 g_hsh[(size_t)NMAX * 3];   // fp16 messages, 48B/row (40B valid)
__device__ float g_hs[(size_t)NMAX * EMB];    // fp32 latent (written by k_final)
__device__ float g_agg[(size_t)NMAX * EMB];   // fp32 aggregation buffer
__device__ int   g_src[EMAX];
__device__ int   g_dst[EMAX];
__device__ float g_fc1[(size_t)NBATCH * HID];
__device__ int   g_is64;

// ---------------- helpers -------------------------------------------------
__device__ __forceinline__ void red_add_v4(float* p, float4 v) {
    asm volatile("red.global.add.v4.f32 [%0], {%1,%2,%3,%4};"
                 :: "l"(p), "f"(v.x), "f"(v.y), "f"(v.z), "f"(v.w) : "memory");
}
__device__ __forceinline__ unsigned cvt_tf32(float f) {
    unsigned u;
    asm("cvt.rna.tf32.f32 %0, %1;" : "=r"(u) : "f"(f));
    return u;
}
__device__ __forceinline__ void mma_tf32(float& d0, float& d1, float& d2, float& d3,
                                         unsigned a0, unsigned a1, unsigned a2, unsigned a3,
                                         unsigned b0, unsigned b1) {
    asm("mma.sync.aligned.m16n8k8.row.col.f32.tf32.tf32.f32 "
        "{%0,%1,%2,%3}, {%4,%5,%6,%7}, {%8,%9}, {%0,%1,%2,%3};"
        : "+f"(d0), "+f"(d1), "+f"(d2), "+f"(d3)
        : "r"(a0), "r"(a1), "r"(a2), "r"(a3), "r"(b0), "r"(b1));
}
// write one node row: o[0..19]*dinv -> fp16x2 packed 48B (+agg fp32 seed)
__device__ __forceinline__ void store_row(int i, const float* o, float dinv) {
    __half2 hh[12];
#pragma unroll
    for (int j = 0; j < 10; j++)
        hh[j] = __floats2half2_rn(o[2*j] * dinv, o[2*j+1] * dinv);
    hh[10] = hh[11] = __float2half2_rn(0.f);
    uint4* hp = &g_hsh[(size_t)i * 3];
    const uint4* src = (const uint4*)hh;
    hp[0] = src[0]; hp[1] = src[1]; hp[2] = src[2];
    float4* ap = (float4*)(g_agg + (size_t)i * EMB);
#pragma unroll
    for (int q = 0; q < EMB / 4; q++)
        ap[q] = make_float4(o[4*q]*dinv, o[4*q+1]*dinv, o[4*q+2]*dinv, o[4*q+3]*dinv);
}

// ---- launch 1: dtype detect + deg := 1 (self loop) -----------------------
__global__ void k_init(const int* __restrict__ ei32, int n) {
    int i = blockIdx.x * blockDim.x + threadIdx.x;
    if (i < n) g_deg[i] = 1;           // self loop
    if (blockIdx.x == 0 && threadIdx.x == 0) {
        int all0 = 1;
        for (int q = 1; q < 257; q += 2)
            if (ei32[q] != 0) { all0 = 0; break; }
        g_is64 = all0;   // int64 little-endian: high words of small values are 0
    }
}

// ---- launch 2: stage edges to int32 + degree count -----------------------
__global__ void k_edges_prep(const void* __restrict__ eiv, int E) {
    int e = blockIdx.x * blockDim.x + threadIdx.x;
    if (e >= E) return;
    int s, d;
    if (g_is64) {
        const long long* p = (const long long*)eiv;
        s = (int)p[e];
        d = (int)p[(size_t)E + e];
    } else {
        const int* p = (const int*)eiv;
        s = p[e];
        d = p[E + e];
    }
    g_src[e] = s;
    g_dst[e] = d;
    atomicAdd(&g_deg[d], 1);
}

// ---- launch 3: msg(fp16) = (x @ W1)*dinv ; agg(fp32) = same (self seed) --
__global__ __launch_bounds__(256) void k_layer1(const float* __restrict__ x,
                                                const float* __restrict__ W,
                                                int n) {
    __shared__ __align__(16) float sW[SEQL * EMB];
    for (int t = threadIdx.x; t < SEQL * EMB; t += 256) sW[t] = W[t];
    __syncthreads();
    int i = blockIdx.x * 256 + threadIdx.x;
    if (i >= n) return;
    float dinv = rsqrtf((float)g_deg[i]);
    g_dinv[i] = dinv;
    float xi[SEQL];
    const float4* xp = (const float4*)(x + (size_t)i * SEQL);
#pragma unroll
    for (int q = 0; q < SEQL / 4; q++) {
        float4 v = __ldg(xp + q);
        xi[4*q] = v.x; xi[4*q+1] = v.y; xi[4*q+2] = v.z; xi[4*q+3] = v.w;
    }
    float o[EMB];
#pragma unroll
    for (int j = 0; j < EMB; j++) o[j] = 0.f;
#pragma unroll
    for (int k = 0; k < SEQL; k++) {
        float xk = xi[k];
#pragma unroll
        for (int q = 0; q < EMB / 4; q++) {
            float4 w = *(const float4*)&sW[k * EMB + 4 * q];
            o[4*q]   = fmaf(xk, w.x, o[4*q]);
            o[4*q+1] = fmaf(xk, w.y, o[4*q+1]);
            o[4*q+2] = fmaf(xk, w.z, o[4*q+2]);
            o[4*q+3] = fmaf(xk, w.w, o[4*q+3]);
        }
    }
    store_row(i, o, dinv);
}

// ---- launch 4 (ncu slot): agg[dst] += msg[src]  (48B fp16 read, fp32 RED)
__global__ __launch_bounds__(256) void k_scatter(int E) {
    int e = blockIdx.x * blockDim.x + threadIdx.x;
    if (e >= E) return;
    int s = g_src[e], d = g_dst[e];
    const uint4* hp = &g_hsh[(size_t)s * 3];
    uint4 u0 = __ldg(hp), u1 = __ldg(hp + 1), u2 = __ldg(hp + 2);
    __half2 hh[12];
    uint4* hv = (uint4*)hh;
    hv[0] = u0; hv[1] = u1; hv[2] = u2;
    float f[EMB];
#pragma unroll
    for (int j = 0; j < 10; j++) {
        float2 t = __half22float2(hh[j]);
        f[2*j] = t.x; f[2*j+1] = t.y;
    }
    float* ap = g_agg + (size_t)d * EMB;
#pragma unroll
    for (int q = 0; q < EMB / 4; q++)
        red_add_v4(ap + 4 * q, make_float4(f[4*q], f[4*q+1], f[4*q+2], f[4*q+3]));
}

// ---- t = relu(agg*dinv + b1);  o = (t @ W2)*dinv -> msg fp16 + agg seed --
__global__ __launch_bounds__(256) void k_layer2(const float* __restrict__ b1,
                                                const float* __restrict__ W,
                                                int n) {
    __shared__ __align__(16) float sW[EMB * EMB];
    __shared__ float sb[EMB];
    for (int t = threadIdx.x; t < EMB * EMB; t += 256) sW[t] = W[t];
    if (threadIdx.x < EMB) sb[threadIdx.x] = b1[threadIdx.x];
    __syncthreads();
    int i = blockIdx.x * 256 + threadIdx.x;
    if (i >= n) return;
    float dinv = g_dinv[i];
    float ti[EMB];
    const float4* ap_in = (const float4*)(g_agg + (size_t)i * EMB);
#pragma unroll
    for (int q = 0; q < EMB / 4; q++) {
        float4 v = ap_in[q];
        ti[4*q]   = fmaxf(fmaf(v.x, dinv, sb[4*q]),   0.f);
        ti[4*q+1] = fmaxf(fmaf(v.y, dinv, sb[4*q+1]), 0.f);
        ti[4*q+2] = fmaxf(fmaf(v.z, dinv, sb[4*q+2]), 0.f);
        ti[4*q+3] = fmaxf(fmaf(v.w, dinv, sb[4*q+3]), 0.f);
    }
    float o[EMB];
#pragma unroll
    for (int j = 0; j < EMB; j++) o[j] = 0.f;
#pragma unroll
    for (int k = 0; k < EMB; k++) {
        float tk = ti[k];
#pragma unroll
        for (int q = 0; q < EMB / 4; q++) {
            float4 w = *(const float4*)&sW[k * EMB + 4 * q];
            o[4*q]   = fmaf(tk, w.x, o[4*q]);
            o[4*q+1] = fmaf(tk, w.y, o[4*q+1]);
            o[4*q+2] = fmaf(tk, w.z, o[4*q+2]);
            o[4*q+3] = fmaf(tk, w.w, o[4*q+3]);
        }
    }
    store_row(i, o, dinv);
}

// ---- latent = relu(agg*dinv + b2)   -> stored fp32 into g_hs -------------
__global__ __launch_bounds__(256) void k_final(const float* __restrict__ b2, int n) {
    __shared__ float sb[EMB];
    if (threadIdx.x < EMB) sb[threadIdx.x] = b2[threadIdx.x];
    __syncthreads();
    int i = blockIdx.x * 256 + threadIdx.x;
    if (i >= n) return;
    float dinv = g_dinv[i];
    const float4* ap = (const float4*)(g_agg + (size_t)i * EMB);
    float4* hp = (float4*)(g_hs + (size_t)i * EMB);
#pragma unroll
    for (int q = 0; q < EMB / 4; q++) {
        float4 v = ap[q];
        v.x = fmaxf(fmaf(v.x, dinv, sb[4*q]),   0.f);
        v.y = fmaxf(fmaf(v.y, dinv, sb[4*q+1]), 0.f);
        v.z = fmaxf(fmaf(v.z, dinv, sb[4*q+2]), 0.f);
        v.w = fmaxf(fmaf(v.w, dinv, sb[4*q+3]), 0.f);
        hp[q] = v;
    }
}

// fc1 (tf32 tensor cores): relu(latent[8192,1640] @ Wf[1640,300] + bf)
// BM=128 BN=64 BK=8; 8 warps (4x2), warp tile 32x32; mma.m16n8k8.
// smem strides 136/72 => (stride%32)==8 => conflict-free frag loads.
#define BM 128
#define BN 64
#define BK 8
__global__ __launch_bounds__(256) void k_fc1(const float* __restrict__ Wf,
                                             const float* __restrict__ bf) {
    __shared__ unsigned As[BK][136];   // [k][m], tf32 bits
    __shared__ unsigned Bs[BK][72];    // [k][n], tf32 bits
    const int tid  = threadIdx.x;
    const int lane = tid & 31;
    const int wid  = tid >> 5;         // 0..7
    const int warp_m = wid & 3;        // 0..3  (32 rows each)
    const int warp_n = wid >> 2;       // 0..1  (32 cols each)
    const int row0 = blockIdx.x * BM;
    const int col0 = blockIdx.y * BN;
    const int g  = lane >> 2;          // 0..7
    const int tg = lane & 3;           // 0..3

    const int arow = tid >> 1;         // 0..127
    const int ak   = (tid & 1) * 4;    // 0 or 4
    const int bk   = tid >> 5;         // 0..7
    const int bn   = (tid & 31) * 2;   // 0..62

    float d[2][4][4];                  // [mtile][ntile][frag]
#pragma unroll
    for (int mt = 0; mt < 2; mt++)
#pragma unroll
        for (int nt = 0; nt < 4; nt++)
#pragma unroll
            for (int q = 0; q < 4; q++) d[mt][nt][q] = 0.f;

    for (int k0 = 0; k0 < LAT; k0 += BK) {
        // A tile: 128 rows x 8 k
        float4 va = *(const float4*)(g_hs + (size_t)(row0 + arow) * LAT + (k0 + ak));
        As[ak + 0][arow] = cvt_tf32(va.x);
        As[ak + 1][arow] = cvt_tf32(va.y);
        As[ak + 2][arow] = cvt_tf32(va.z);
        As[ak + 3][arow] = cvt_tf32(va.w);
        // B tile: 8 k x 64 n (guarded, zero-pad)
        {
            int gc = col0 + bn;
            float2 vb = make_float2(0.f, 0.f);
            if (gc < HID)
                vb = *(const float2*)(Wf + (size_t)(k0 + bk) * HID + gc);
            Bs[bk][bn]     = cvt_tf32(vb.x);
            Bs[bk][bn + 1] = cvt_tf32(vb.y);
        }
        __syncthreads();

        // fragments + mma
        unsigned a[2][4], b[4][2];
#pragma unroll
        for (int mt = 0; mt < 2; mt++) {
            int wr = warp_m * 32 + mt * 16 + g;
            a[mt][0] = As[tg][wr];
            a[mt][1] = As[tg][wr + 8];
            a[mt][2] = As[tg + 4][wr];
            a[mt][3] = As[tg + 4][wr + 8];
        }
#pragma unroll
        for (int nt = 0; nt < 4; nt++) {
            int wc = warp_n * 32 + nt * 8 + g;
            b[nt][0] = Bs[tg][wc];
            b[nt][1] = Bs[tg + 4][wc];
        }
#pragma unroll
        for (int mt = 0; mt < 2; mt++)
#pragma unroll
            for (int nt = 0; nt < 4; nt++)
                mma_tf32(d[mt][nt][0], d[mt][nt][1], d[mt][nt][2], d[mt][nt][3],
                         a[mt][0], a[mt][1], a[mt][2], a[mt][3],
                         b[nt][0], b[nt][1]);
        __syncthreads();
    }

    // epilogue: bias + relu -> g_fc1 (float2 stores; HID even, cols even)
#pragma unroll
    for (int mt = 0; mt < 2; mt++) {
        int r = row0 + warp_m * 32 + mt * 16 + g;
#pragma unroll
        for (int nt = 0; nt < 4; nt++) {
            int c = col0 + warp_n * 32 + nt * 8 + tg * 2;
            if (c < HID) {
                float b0 = bf[c], b1 = bf[c + 1];
                float2 lo = make_float2(fmaxf(d[mt][nt][0] + b0, 0.f),
                                        fmaxf(d[mt][nt][1] + b1, 0.f));
                float2 hi = make_float2(fmaxf(d[mt][nt][2] + b0, 0.f),
                                        fmaxf(d[mt][nt][3] + b1, 0.f));
                *(float2*)(g_fc1 + (size_t)r * HID + c)       = lo;
                *(float2*)(g_fc1 + (size_t)(r + 8) * HID + c) = hi;
            }
        }
    }
}

// out: [8192,300] @ [300,22] + out_b
__global__ __launch_bounds__(256) void k_out(const float* __restrict__ Wo,
                                             const float* __restrict__ bo,
                                             float* __restrict__ out) {
    __shared__ float sW[HID * NC];
    __shared__ float sb[NC];
    for (int t = threadIdx.x; t < HID * NC; t += 256) sW[t] = Wo[t];
    if (threadIdx.x < NC) sb[threadIdx.x] = bo[threadIdx.x];
    __syncthreads();
    int w = threadIdx.x >> 5, lane = threadIdx.x & 31;
    int rbase = blockIdx.x * 64 + w * 8;
#pragma unroll 1
    for (int r8 = 0; r8 < 8; r8++) {
        int r = rbase + r8;
        const float4* fr4 = (const float4*)(g_fc1 + (size_t)r * HID);
        if (lane < NC) {
            float accv = 0.f;
#pragma unroll 5
            for (int k4 = 0; k4 < HID / 4; k4++) {
                float4 v = fr4[k4];
                int k = 4 * k4;
                accv = fmaf(v.x, sW[(k + 0) * NC + lane], accv);
                accv = fmaf(v.y, sW[(k + 1) * NC + lane], accv);
                accv = fmaf(v.z, sW[(k + 2) * NC + lane], accv);
                accv = fmaf(v.w, sW[(k + 3) * NC + lane], accv);
            }
            out[(size_t)r * NC + lane] = accv + sb[lane];
        }
    }
}

// ---------------- launch --------------------------------------------------
extern "C" void kernel_launch(void* const* d_in, const int* in_sizes, int n_in,
                              void* d_out, int out_size) {
    const float* x    = (const float*)d_in[0];
    const void*  ei   = d_in[1];
    const float* W1   = (const float*)d_in[3];
    const float* b1   = (const float*)d_in[4];
    const float* W2   = (const float*)d_in[5];
    const float* b2   = (const float*)d_in[6];
    const float* fc1W = (const float*)d_in[7];
    const float* fc1b = (const float*)d_in[8];
    const float* outW = (const float*)d_in[9];
    const float* outb = (const float*)d_in[10];
    float* out = (float*)d_out;

    int N = in_sizes[0] / SEQL;
    int E = in_sizes[1] / 2;
    int rows = out_size / NC;                // 8192
    int nb = (N + 255) / 256;
    int eb = (E + 255) / 256;

    k_init<<<nb, 256>>>((const int*)ei, N);     // 1
    k_edges_prep<<<eb, 256>>>(ei, E);           // 2
    k_layer1<<<nb, 256>>>(x, W1, N);            // 3
    k_scatter<<<eb, 256>>>(E);                  // 4  <-- ncu slot (sentinel)
    k_layer2<<<nb, 256>>>(b1, W2, N);           // 5
    k_scatter<<<eb, 256>>>(E);                  // 6
    k_final<<<nb, 256>>>(b2, N);                // 7
    dim3 gfc(rows / BM, (HID + BN - 1) / BN);
    k_fc1<<<gfc, 256>>>(fc1W, fc1b);            // 8
    k_out<<<rows / 64, 256>>>(outW, outb, out); // 9
}

// round 13
// speedup vs baseline: 1.3166x; 1.0069x over previous
#include <cuda_runtime.h>
#include <cuda_fp16.h>

#define SEQL 20
#define EMB  20
#define NMAX 671744
#define EMAX 4000000
#define NBATCH 8192
#define HID  300
#define NC   22
#define LAT  1640   // 82*20

// ---------------- scratch (static device globals; no runtime alloc) -------
__device__ int   g_deg[NMAX];
__device__ float g_dinv[NMAX];
__device__ __align__(16) uint4 g_hsh[(size_t)NMAX * 3];   // fp16 messages, 48B/row (40B valid)
__device__ float g_agg[(size_t)NMAX * EMB];   // fp32 aggregation buffer
__device__ int   g_src[EMAX];
__device__ int   g_dst[EMAX];
__device__ float g_fc1[(size_t)NBATCH * HID];
__device__ int   g_is64;

// ---------------- helpers -------------------------------------------------
__device__ __forceinline__ void red_add_v4(float* p, float4 v) {
    asm volatile("red.global.add.v4.f32 [%0], {%1,%2,%3,%4};"
                 :: "l"(p), "f"(v.x), "f"(v.y), "f"(v.z), "f"(v.w) : "memory");
}
__device__ __forceinline__ unsigned cvt_tf32(float f) {
    unsigned u;
    asm("cvt.rna.tf32.f32 %0, %1;" : "=r"(u) : "f"(f));
    return u;
}
__device__ __forceinline__ void mma_tf32(float& d0, float& d1, float& d2, float& d3,
                                         unsigned a0, unsigned a1, unsigned a2, unsigned a3,
                                         unsigned b0, unsigned b1) {
    asm("mma.sync.aligned.m16n8k8.row.col.f32.tf32.tf32.f32 "
        "{%0,%1,%2,%3}, {%4,%5,%6,%7}, {%8,%9}, {%0,%1,%2,%3};"
        : "+f"(d0), "+f"(d1), "+f"(d2), "+f"(d3)
        : "r"(a0), "r"(a1), "r"(a2), "r"(a3), "r"(b0), "r"(b1));
}
// write one node row: o[0..19]*dinv -> fp16x2 packed 48B (+agg fp32 seed)
__device__ __forceinline__ void store_row(int i, const float* o, float dinv) {
    __half2 hh[12];
#pragma unroll
    for (int j = 0; j < 10; j++)
        hh[j] = __floats2half2_rn(o[2*j] * dinv, o[2*j+1] * dinv);
    hh[10] = hh[11] = __float2half2_rn(0.f);
    uint4* hp = &g_hsh[(size_t)i * 3];
    const uint4* src = (const uint4*)hh;
    hp[0] = src[0]; hp[1] = src[1]; hp[2] = src[2];
    float4* ap = (float4*)(g_agg + (size_t)i * EMB);
#pragma unroll
    for (int q = 0; q < EMB / 4; q++)
        ap[q] = make_float4(o[4*q]*dinv, o[4*q+1]*dinv, o[4*q+2]*dinv, o[4*q+3]*dinv);
}

// ---- launch 1: dtype detect + deg := 1 (self loop) -----------------------
__global__ void k_init(const int* __restrict__ ei32, int n) {
    int i = blockIdx.x * blockDim.x + threadIdx.x;
    if (i < n) g_deg[i] = 1;           // self loop
    if (blockIdx.x == 0 && threadIdx.x == 0) {
        int all0 = 1;
        for (int q = 1; q < 257; q += 2)
            if (ei32[q] != 0) { all0 = 0; break; }
        g_is64 = all0;   // int64 little-endian: high words of small values are 0
    }
}

// ---- launch 2: stage edges to int32 + degree count -----------------------
__global__ void k_edges_prep(const void* __restrict__ eiv, int E) {
    int e = blockIdx.x * blockDim.x + threadIdx.x;
    if (e >= E) return;
    int s, d;
    if (g_is64) {
        const long long* p = (const long long*)eiv;
        s = (int)p[e];
        d = (int)p[(size_t)E + e];
    } else {
        const int* p = (const int*)eiv;
        s = p[e];
        d = p[E + e];
    }
    g_src[e] = s;
    g_dst[e] = d;
    atomicAdd(&g_deg[d], 1);
}

// ---- launch 3: msg(fp16) = (x @ W1)*dinv ; agg(fp32) = same (self seed) --
__global__ __launch_bounds__(256) void k_layer1(const float* __restrict__ x,
                                                const float* __restrict__ W,
                                                int n) {
    __shared__ __align__(16) float sW[SEQL * EMB];
    for (int t = threadIdx.x; t < SEQL * EMB; t += 256) sW[t] = W[t];
    __syncthreads();
    int i = blockIdx.x * 256 + threadIdx.x;
    if (i >= n) return;
    float dinv = rsqrtf((float)g_deg[i]);
    g_dinv[i] = dinv;
    float xi[SEQL];
    const float4* xp = (const float4*)(x + (size_t)i * SEQL);
#pragma unroll
    for (int q = 0; q < SEQL / 4; q++) {
        float4 v = __ldg(xp + q);
        xi[4*q] = v.x; xi[4*q+1] = v.y; xi[4*q+2] = v.z; xi[4*q+3] = v.w;
    }
    float o[EMB];
#pragma unroll
    for (int j = 0; j < EMB; j++) o[j] = 0.f;
#pragma unroll
    for (int k = 0; k < SEQL; k++) {
        float xk = xi[k];
#pragma unroll
        for (int q = 0; q < EMB / 4; q++) {
            float4 w = *(const float4*)&sW[k * EMB + 4 * q];
            o[4*q]   = fmaf(xk, w.x, o[4*q]);
            o[4*q+1] = fmaf(xk, w.y, o[4*q+1]);
            o[4*q+2] = fmaf(xk, w.z, o[4*q+2]);
            o[4*q+3] = fmaf(xk, w.w, o[4*q+3]);
        }
    }
    store_row(i, o, dinv);
}

// ---- launch 4 (ncu slot): agg[dst] += msg[src]  (48B fp16 read, fp32 RED)
__global__ __launch_bounds__(256) void k_scatter(int E) {
    int e = blockIdx.x * blockDim.x + threadIdx.x;
    if (e >= E) return;
    int s = g_src[e], d = g_dst[e];
    const uint4* hp = &g_hsh[(size_t)s * 3];
    uint4 u0 = __ldg(hp), u1 = __ldg(hp + 1), u2 = __ldg(hp + 2);
    __half2 hh[12];
    uint4* hv = (uint4*)hh;
    hv[0] = u0; hv[1] = u1; hv[2] = u2;
    float f[EMB];
#pragma unroll
    for (int j = 0; j < 10; j++) {
        float2 t = __half22float2(hh[j]);
        f[2*j] = t.x; f[2*j+1] = t.y;
    }
    float* ap = g_agg + (size_t)d * EMB;
#pragma unroll
    for (int q = 0; q < EMB / 4; q++)
        red_add_v4(ap + 4 * q, make_float4(f[4*q], f[4*q+1], f[4*q+2], f[4*q+3]));
}

// ---- t = relu(agg*dinv + b1);  o = (t @ W2)*dinv -> msg fp16 + agg seed --
__global__ __launch_bounds__(256) void k_layer2(const float* __restrict__ b1,
                                                const float* __restrict__ W,
                                                int n) {
    __shared__ __align__(16) float sW[EMB * EMB];
    __shared__ float sb[EMB];
    for (int t = threadIdx.x; t < EMB * EMB; t += 256) sW[t] = W[t];
    if (threadIdx.x < EMB) sb[threadIdx.x] = b1[threadIdx.x];
    __syncthreads();
    int i = blockIdx.x * 256 + threadIdx.x;
    if (i >= n) return;
    float dinv = g_dinv[i];
    float ti[EMB];
    const float4* ap_in = (const float4*)(g_agg + (size_t)i * EMB);
#pragma unroll
    for (int q = 0; q < EMB / 4; q++) {
        float4 v = ap_in[q];
        ti[4*q]   = fmaxf(fmaf(v.x, dinv, sb[4*q]),   0.f);
        ti[4*q+1] = fmaxf(fmaf(v.y, dinv, sb[4*q+1]), 0.f);
        ti[4*q+2] = fmaxf(fmaf(v.z, dinv, sb[4*q+2]), 0.f);
        ti[4*q+3] = fmaxf(fmaf(v.w, dinv, sb[4*q+3]), 0.f);
    }
    float o[EMB];
#pragma unroll
    for (int j = 0; j < EMB; j++) o[j] = 0.f;
#pragma unroll
    for (int k = 0; k < EMB; k++) {
        float tk = ti[k];
#pragma unroll
        for (int q = 0; q < EMB / 4; q++) {
            float4 w = *(const float4*)&sW[k * EMB + 4 * q];
            o[4*q]   = fmaf(tk, w.x, o[4*q]);
            o[4*q+1] = fmaf(tk, w.y, o[4*q+1]);
            o[4*q+2] = fmaf(tk, w.z, o[4*q+2]);
            o[4*q+3] = fmaf(tk, w.w, o[4*q+3]);
        }
    }
    store_row(i, o, dinv);
}

// fc1 (tf32 tensor cores, fused final): A[r][c] = relu(agg[r*1640+c]*dinv + b2)
// computed on the fly in the A-tile load; C = relu(A @ Wf + bf).
// BM=128 BN=64 BK=16; 8 warps (4x2), warp tile 32x32; mma.m16n8k8.
#define BM 128
#define BN 64
#define BK 16
__global__ __launch_bounds__(256) void k_fc1(const float* __restrict__ Wf,
                                             const float* __restrict__ bf,
                                             const float* __restrict__ b2) {
    __shared__ unsigned As[BK][136];   // [k][m], tf32 bits
    __shared__ unsigned Bs[BK][72];    // [k][n], tf32 bits
    __shared__ float sb2[EMB];
    const int tid  = threadIdx.x;
    const int lane = tid & 31;
    const int wid  = tid >> 5;         // 0..7
    const int warp_m = wid & 3;        // 0..3  (32 rows each)
    const int warp_n = wid >> 2;       // 0..1  (32 cols each)
    const int row0 = blockIdx.x * BM;
    const int col0 = blockIdx.y * BN;
    const int g  = lane >> 2;          // 0..7
    const int tg = lane & 3;           // 0..3

    const int arow = tid >> 1;         // 0..127
    const int ak   = (tid & 1) * 8;    // 0 or 8  (two float4s each)
    const int bk   = tid >> 4;         // 0..15
    const int bn   = (tid & 15) * 4;   // 0..60

    if (tid < EMB) sb2[tid] = b2[tid];

    float d[2][4][4];                  // [mtile][ntile][frag]
#pragma unroll
    for (int mt = 0; mt < 2; mt++)
#pragma unroll
        for (int nt = 0; nt < 4; nt++)
#pragma unroll
            for (int q = 0; q < 4; q++) d[mt][nt][q] = 0.f;

    __syncthreads();   // sb2 ready

    const float* arowp = g_agg + (size_t)(row0 + arow) * LAT;
    const int  anode0  = (row0 + arow) * 82;

    for (int k0 = 0; k0 < LAT; k0 += BK) {
        // A tile: 128 rows x 16 k, fused relu(agg*dinv + b2), tail zero-pad
#pragma unroll
        for (int h = 0; h < 2; h++) {
            int c = k0 + ak + 4 * h;          // column, multiple of 4; one node
            if (c < LAT) {
                float4 va = *(const float4*)(arowp + c);
                float dv = __ldg(&g_dinv[anode0 + c / 20]);
                int f0 = c % 20;
                As[ak + 4*h + 0][arow] = cvt_tf32(fmaxf(fmaf(va.x, dv, sb2[f0 + 0]), 0.f));
                As[ak + 4*h + 1][arow] = cvt_tf32(fmaxf(fmaf(va.y, dv, sb2[f0 + 1]), 0.f));
                As[ak + 4*h + 2][arow] = cvt_tf32(fmaxf(fmaf(va.z, dv, sb2[f0 + 2]), 0.f));
                As[ak + 4*h + 3][arow] = cvt_tf32(fmaxf(fmaf(va.w, dv, sb2[f0 + 3]), 0.f));
            } else {
                As[ak + 4*h + 0][arow] = 0u;
                As[ak + 4*h + 1][arow] = 0u;
                As[ak + 4*h + 2][arow] = 0u;
                As[ak + 4*h + 3][arow] = 0u;
            }
        }
        // B tile: 16 k x 64 n (guarded both dims, zero-pad)
        {
            int gc = col0 + bn;
            float4 vb = make_float4(0.f, 0.f, 0.f, 0.f);
            if (gc < HID && (k0 + bk) < LAT)
                vb = *(const float4*)(Wf + (size_t)(k0 + bk) * HID + gc);
            Bs[bk][bn]     = cvt_tf32(vb.x);
            Bs[bk][bn + 1] = cvt_tf32(vb.y);
            Bs[bk][bn + 2] = cvt_tf32(vb.z);
            Bs[bk][bn + 3] = cvt_tf32(vb.w);
        }
        __syncthreads();

        // two k=8 sub-steps
#pragma unroll
        for (int kk = 0; kk < BK; kk += 8) {
            unsigned a[2][4], b[4][2];
#pragma unroll
            for (int mt = 0; mt < 2; mt++) {
                int wr = warp_m * 32 + mt * 16 + g;
                a[mt][0] = As[kk + tg][wr];
                a[mt][1] = As[kk + tg][wr + 8];
                a[mt][2] = As[kk + tg + 4][wr];
                a[mt][3] = As[kk + tg + 4][wr + 8];
            }
#pragma unroll
            for (int nt = 0; nt < 4; nt++) {
                int wc = warp_n * 32 + nt * 8 + g;
                b[nt][0] = Bs[kk + tg][wc];
                b[nt][1] = Bs[kk + tg + 4][wc];
            }
#pragma unroll
            for (int mt = 0; mt < 2; mt++)
#pragma unroll
                for (int nt = 0; nt < 4; nt++)
                    mma_tf32(d[mt][nt][0], d[mt][nt][1], d[mt][nt][2], d[mt][nt][3],
                             a[mt][0], a[mt][1], a[mt][2], a[mt][3],
                             b[nt][0], b[nt][1]);
        }
        __syncthreads();
    }

    // epilogue: bias + relu -> g_fc1 (float2 stores; HID even, cols even)
#pragma unroll
    for (int mt = 0; mt < 2; mt++) {
        int r = row0 + warp_m * 32 + mt * 16 + g;
#pragma unroll
        for (int nt = 0; nt < 4; nt++) {
            int c = col0 + warp_n * 32 + nt * 8 + tg * 2;
            if (c < HID) {
                float b0 = bf[c], b1 = bf[c + 1];
                float2 lo = make_float2(fmaxf(d[mt][nt][0] + b0, 0.f),
                                        fmaxf(d[mt][nt][1] + b1, 0.f));
                float2 hi = make_float2(fmaxf(d[mt][nt][2] + b0, 0.f),
                                        fmaxf(d[mt][nt][3] + b1, 0.f));
                *(float2*)(g_fc1 + (size_t)r * HID + c)       = lo;
                *(float2*)(g_fc1 + (size_t)(r + 8) * HID + c) = hi;
            }
        }
    }
}

// out: [8192,300] @ [300,22] + out_b
__global__ __launch_bounds__(256) void k_out(const float* __restrict__ Wo,
                                             const float* __restrict__ bo,
                                             float* __restrict__ out) {
    __shared__ float sW[HID * NC];
    __shared__ float sb[NC];
    for (int t = threadIdx.x; t < HID * NC; t += 256) sW[t] = Wo[t];
    if (threadIdx.x < NC) sb[threadIdx.x] = bo[threadIdx.x];
    __syncthreads();
    int w = threadIdx.x >> 5, lane = threadIdx.x & 31;
    int rbase = blockIdx.x * 64 + w * 8;
#pragma unroll 1
    for (int r8 = 0; r8 < 8; r8++) {
        int r = rbase + r8;
        const float4* fr4 = (const float4*)(g_fc1 + (size_t)r * HID);
        if (lane < NC) {
            float accv = 0.f;
#pragma unroll 5
            for (int k4 = 0; k4 < HID / 4; k4++) {
                float4 v = fr4[k4];
                int k = 4 * k4;
                accv = fmaf(v.x, sW[(k + 0) * NC + lane], accv);
                accv = fmaf(v.y, sW[(k + 1) * NC + lane], accv);
                accv = fmaf(v.z, sW[(k + 2) * NC + lane], accv);
                accv = fmaf(v.w, sW[(k + 3) * NC + lane], accv);
            }
            out[(size_t)r * NC + lane] = accv + sb[lane];
        }
    }
}

// ---------------- launch --------------------------------------------------
extern "C" void kernel_launch(void* const* d_in, const int* in_sizes, int n_in,
                              void* d_out, int out_size) {
    const float* x    = (const float*)d_in[0];
    const void*  ei   = d_in[1];
    const float* W1   = (const float*)d_in[3];
    const float* b1   = (const float*)d_in[4];
    const float* W2   = (const float*)d_in[5];
    const float* b2   = (const float*)d_in[6];
    const float* fc1W = (const float*)d_in[7];
    const float* fc1b = (const float*)d_in[8];
    const float* outW = (const float*)d_in[9];
    const float* outb = (const float*)d_in[10];
    float* out = (float*)d_out;

    int N = in_sizes[0] / SEQL;
    int E = in_sizes[1] / 2;
    int rows = out_size / NC;                // 8192
    int nb = (N + 255) / 256;
    int eb = (E + 255) / 256;

    k_init<<<nb, 256>>>((const int*)ei, N);     // 1
    k_edges_prep<<<eb, 256>>>(ei, E);           // 2
    k_layer1<<<nb, 256>>>(x, W1, N);            // 3
    k_scatter<<<eb, 256>>>(E);                  // 4  <-- ncu slot (sentinel)
    k_layer2<<<nb, 256>>>(b1, W2, N);           // 5
    k_scatter<<<eb, 256>>>(E);                  // 6
    dim3 gfc(rows / BM, (HID + BN - 1) / BN);
    k_fc1<<<gfc, 256>>>(fc1W, fc1b, b2);        // 7 (fused final)
    k_out<<<rows / 64, 256>>>(outW, outb, out); // 8
}